// round 5
// baseline (speedup 1.0000x reference)
#include <cuda_runtime.h>

// Causal FullAttention: B=4, L=2048, H=16, E=64, fp32.
// out[b,l,h,d] = softmax_s( (q[b,l,h,:].k[b,s,h,:]) / sqrt(E), causal ) . v[b,s,h,d]
//
// Flash-attention-2 style: one CTA per (q_tile=64 rows, h, b), online softmax,
// K/V streamed in 64-row tiles. 256 threads: thread t owns query row r = t>>2
// and the strided quarter q4 = t&3 of key-columns / value-dims.
// All smem tiles padded to 17 float4 per row -> every LDS.128 in the inner
// loops lands in 4 distinct bank groups (conflict-free).

#define B_DIM 4
#define L_DIM 2048
#define H_DIM 16
#define E_DIM 64
#define BR 64
#define BC 64
#define NTHREADS 256

// float4 row strides
#define TPAD 17              // padded float4 row stride for Q/K/V tiles
#define SPAD 68              // padded float row stride for the P (prob) tile

// dynamic smem: Qs + Ks + Vs (each 64*17 float4) + Ss (64*68 float)
#define SMEM_BYTES (3 * BR * TPAD * 16 + BR * SPAD * 4)

__global__ __launch_bounds__(NTHREADS)
void fa_causal_kernel(const float* __restrict__ Q,
                      const float* __restrict__ K,
                      const float* __restrict__ V,
                      float* __restrict__ O)
{
    extern __shared__ float smem[];
    float4* Qs = reinterpret_cast<float4*>(smem);       // [64][17] f4
    float4* Ks = Qs + BR * TPAD;                        // [64][17] f4
    float4* Vs = Ks + BR * TPAD;                        // [64][17] f4
    float*  Ss = reinterpret_cast<float*>(Vs + BR * TPAD); // [64][68] f

    const int qt = blockIdx.x;   // query tile (0..31)
    const int h  = blockIdx.y;   // head
    const int b  = blockIdx.z;   // batch
    const int t  = threadIdx.x;
    const int r  = t >> 2;       // query row within tile (0..63)
    const int q4 = t & 3;        // quarter index (0..3)

    // Global row stride between consecutive sequence positions: H*E floats = 256 f4.
    const size_t seq_stride_f4 = (size_t)H_DIM * E_DIM / 4;   // 256

    // ---- load Q tile (coalesced: 1024 float4, 4 per thread) ----
    {
        const float4* Qg = reinterpret_cast<const float4*>(
            Q + (((size_t)b * L_DIM + (size_t)qt * BR) * H_DIM + h) * E_DIM);
        #pragma unroll
        for (int it = 0; it < 4; ++it) {
            int i   = t + it * NTHREADS;
            int row = i >> 4;
            int c4  = i & 15;
            Qs[row * TPAD + c4] = Qg[(size_t)row * seq_stride_f4 + c4];
        }
    }
    __syncthreads();

    const float scale = 0.125f;  // 1/sqrt(64), T=1
    float m = -1e30f;
    float l = 0.f;
    float4 acc[4];
    #pragma unroll
    for (int j = 0; j < 4; ++j) acc[j] = make_float4(0.f, 0.f, 0.f, 0.f);

    for (int kt = 0; kt <= qt; ++kt) {
        __syncthreads();  // previous tile's Vs reads complete before overwrite

        // ---- load K,V tiles ----
        {
            const float4* Kg = reinterpret_cast<const float4*>(
                K + (((size_t)b * L_DIM + (size_t)kt * BC) * H_DIM + h) * E_DIM);
            const float4* Vg = reinterpret_cast<const float4*>(
                V + (((size_t)b * L_DIM + (size_t)kt * BC) * H_DIM + h) * E_DIM);
            #pragma unroll
            for (int it = 0; it < 4; ++it) {
                int i   = t + it * NTHREADS;
                int row = i >> 4;
                int c4  = i & 15;
                Ks[row * TPAD + c4] = Kg[(size_t)row * seq_stride_f4 + c4];
                Vs[row * TPAD + c4] = Vg[(size_t)row * seq_stride_f4 + c4];
            }
        }
        __syncthreads();

        // ---- S = Q K^T : thread computes 16 strided columns c = q4 + 4*cc ----
        float s[16];
        #pragma unroll
        for (int cc = 0; cc < 16; ++cc) s[cc] = 0.f;

        #pragma unroll 4
        for (int e4 = 0; e4 < 16; ++e4) {
            float4 qv = Qs[r * TPAD + e4];
            #pragma unroll
            for (int cc = 0; cc < 16; ++cc) {
                float4 kv = Ks[(q4 + 4 * cc) * TPAD + e4];
                s[cc] += qv.x * kv.x + qv.y * kv.y + qv.z * kv.z + qv.w * kv.w;
            }
        }

        #pragma unroll
        for (int cc = 0; cc < 16; ++cc) s[cc] *= scale;

        // causal mask only on the diagonal tile
        if (kt == qt) {
            #pragma unroll
            for (int cc = 0; cc < 16; ++cc) {
                int kj = q4 + 4 * cc;
                if (kj > r) s[cc] = -1e30f;
            }
        }

        // ---- online softmax (row stats across the 4 owning lanes) ----
        float mloc = s[0];
        #pragma unroll
        for (int cc = 1; cc < 16; ++cc) mloc = fmaxf(mloc, s[cc]);
        mloc = fmaxf(mloc, __shfl_xor_sync(0xffffffffu, mloc, 1));
        mloc = fmaxf(mloc, __shfl_xor_sync(0xffffffffu, mloc, 2));

        float mnew = fmaxf(m, mloc);
        float corr = __expf(m - mnew);   // first tile: exp(-1e30 - finite) = 0, no NaN

        float psum = 0.f;
        #pragma unroll
        for (int cc = 0; cc < 16; ++cc) {
            float p = __expf(s[cc] - mnew);  // masked -> exp(~-1e30) underflows to 0
            s[cc] = p;
            psum += p;
        }
        psum += __shfl_xor_sync(0xffffffffu, psum, 1);
        psum += __shfl_xor_sync(0xffffffffu, psum, 2);

        l = l * corr + psum;
        m = mnew;
        #pragma unroll
        for (int j = 0; j < 4; ++j) {
            acc[j].x *= corr; acc[j].y *= corr; acc[j].z *= corr; acc[j].w *= corr;
        }

        // ---- stage P through smem (row's 4 producers are in this warp) ----
        #pragma unroll
        for (int cc = 0; cc < 16; ++cc)
            Ss[r * SPAD + q4 + 4 * cc] = s[cc];
        __syncwarp();

        // ---- O += P V : thread accumulates strided dim-chunks d4 = q4 + 4*j ----
        #pragma unroll 8
        for (int c = 0; c < BC; ++c) {
            float p = Ss[r * SPAD + c];
            #pragma unroll
            for (int j = 0; j < 4; ++j) {
                float4 v = Vs[c * TPAD + q4 + 4 * j];
                acc[j].x += p * v.x;
                acc[j].y += p * v.y;
                acc[j].z += p * v.z;
                acc[j].w += p * v.w;
            }
        }
        __syncwarp();
    }

    // ---- epilogue: normalize and store ----
    float inv = 1.f / l;
    float4* Og = reinterpret_cast<float4*>(
        O + (((size_t)b * L_DIM + (size_t)qt * BR + r) * H_DIM + h) * E_DIM);
    #pragma unroll
    for (int j = 0; j < 4; ++j) {
        float4 o = acc[j];
        o.x *= inv; o.y *= inv; o.z *= inv; o.w *= inv;
        Og[q4 + 4 * j] = o;
    }
}

extern "C" void kernel_launch(void* const* d_in, const int* in_sizes, int n_in,
                              void* d_out, int out_size)
{
    const float* Q = (const float*)d_in[0];  // queries [B,L,H,E]
    const float* K = (const float*)d_in[1];  // keys    [B,L,H,E]
    const float* V = (const float*)d_in[2];  // values  [B,L,H,E]
    float* O = (float*)d_out;                // out     [B,L,H,E]

    // 69,632 B dynamic smem > 48 KB default -> opt in (deterministic, capture-safe).
    cudaFuncSetAttribute(fa_causal_kernel,
                         cudaFuncAttributeMaxDynamicSharedMemorySize, SMEM_BYTES);

    dim3 grid(L_DIM / BR, H_DIM, B_DIM);   // 32 x 16 x 4 = 2048 CTAs
    fa_causal_kernel<<<grid, NTHREADS, SMEM_BYTES>>>(Q, K, V, O);
}

// round 6
// speedup vs baseline: 2.3180x; 2.3180x over previous
#include <cuda_runtime.h>

// Causal FullAttention, B=4, L=2048, H=16, E=64, fp32.
// Flash-attention-2 style, BR=BC=128, 256 threads, 8x8 register micro-tiles.
//
// Thread t: tr = t>>4 (0..15) owns query rows 8tr..8tr+7;
//           tc = t&15  (0..15) owns key cols 8tc..8tc+7 (for S) and
//                              value dims 4tc..4tc+3 (for O).
// Row softmax stats live in the 16-lane half-warp group (tr fixed) -> shfl_xor 1,2,4,8.
//
// Smem bank discipline (all analysis at float4 = 16B granularity, 8 bank-groups):
//  - Qs/Ks [row][e4^( (row>>3)&7 )], stride 17 f4: K reads (16 distinct f4) = 2 wf,
//    Q reads (2 distinct, bcast) = 1 wf; transposed-free stores = 4 wf.
//  - Vs natural [row][c4], stride 17: PV reads (16 distinct, contiguous row) = 2 wf.
//  - Ps [row][ (c4^(c4>>3)) ^ ((row>>3)&7) ], stride 32: stores 4 wf (optimal for
//    32 distinct f4), reads 1 wf (2 bcast addrs in distinct bank-groups).

#define L_DIM 2048
#define H_DIM 16
#define E_DIM 64
#define BR 128
#define BC 128
#define NTH 256

#define TS 17            // f4 row stride for Qs/Ks/Vs
#define PS 32            // f4 row stride for Ps

#define SMEM_F4 (3 * 128 * TS + 128 * PS)
#define SMEM_BYTES (SMEM_F4 * 16)   // 169,984 B

__global__ __launch_bounds__(NTH, 1)
void fa_causal_kernel(const float* __restrict__ Q,
                      const float* __restrict__ K,
                      const float* __restrict__ V,
                      float* __restrict__ O)
{
    extern __shared__ float4 sm4[];
    float4* Qs = sm4;               // [128][17]
    float4* Ks = Qs + 128 * TS;     // [128][17]
    float4* Vs = Ks + 128 * TS;     // [128][17]
    float4* Ps = Vs + 128 * TS;     // [128][32]

    const int t  = threadIdx.x;
    const int tr = t >> 4;          // query-row group
    const int tc = t & 15;          // key-col / dim group
    const int qt = 15 - (int)blockIdx.x;  // heavy tiles launch first
    const int h  = blockIdx.y;
    const int b  = blockIdx.z;

    const int xq = tr & 7;          // swizzle key for this thread's Q/P rows
    const int xk = tc & 7;          // swizzle key for this thread's K rows

    // f4 index of (b, l, h, 0): (b*L + l)*256 + h*16
    const float4* Qg = (const float4*)Q + ((size_t)(b * L_DIM + qt * BR)) * 256 + h * 16;
    const float4* Kg = (const float4*)K + ((size_t)b * L_DIM) * 256 + h * 16;
    const float4* Vg = (const float4*)V + ((size_t)b * L_DIM) * 256 + h * 16;

    // ---- load Q tile once, pre-scaled by 1/sqrt(64)=0.125 (exact pow2) ----
    #pragma unroll
    for (int it = 0; it < 8; ++it) {
        int i   = t + it * NTH;
        int row = i >> 4;
        int c4  = i & 15;
        float4 q = Qg[row * 256 + c4];
        q.x *= 0.125f; q.y *= 0.125f; q.z *= 0.125f; q.w *= 0.125f;
        Qs[row * TS + (c4 ^ ((row >> 3) & 7))] = q;
    }

    float4 acc[8];
    float m[8], l[8];
    #pragma unroll
    for (int i = 0; i < 8; ++i) {
        acc[i] = make_float4(0.f, 0.f, 0.f, 0.f);
        m[i] = -1e30f;
        l[i] = 0.f;
    }

    for (int kt = 0; kt <= qt; ++kt) {
        __syncthreads();   // prior tile's smem reads complete (also orders Q store, 1st iter)

        // ---- load K (e4-swizzled) and V (natural) tiles ----
        const float4* Kt = Kg + (size_t)kt * BC * 256;
        const float4* Vt = Vg + (size_t)kt * BC * 256;
        #pragma unroll
        for (int it = 0; it < 8; ++it) {
            int i   = t + it * NTH;
            int row = i >> 4;
            int c4  = i & 15;
            Ks[row * TS + (c4 ^ ((row >> 3) & 7))] = Kt[row * 256 + c4];
            Vs[row * TS + c4]                      = Vt[row * 256 + c4];
        }
        __syncthreads();

        // ---- S = Q K^T : 8x8 micro-tile via rank-1 updates over e4 chunks ----
        float s[8][8];
        #pragma unroll
        for (int i = 0; i < 8; ++i)
            #pragma unroll
            for (int j = 0; j < 8; ++j) s[i][j] = 0.f;

        #pragma unroll 2
        for (int e4 = 0; e4 < 16; ++e4) {
            float4 qv[8];
            #pragma unroll
            for (int i = 0; i < 8; ++i)
                qv[i] = Qs[(8 * tr + i) * TS + (e4 ^ xq)];
            #pragma unroll
            for (int j = 0; j < 8; ++j) {
                float4 kv = Ks[(8 * tc + j) * TS + (e4 ^ xk)];
                #pragma unroll
                for (int i = 0; i < 8; ++i)
                    s[i][j] += qv[i].x * kv.x + qv[i].y * kv.y
                             + qv[i].z * kv.z + qv[i].w * kv.w;
            }
        }

        // ---- causal mask: only the diagonal tile ----
        if (kt == qt) {
            #pragma unroll
            for (int i = 0; i < 8; ++i)
                #pragma unroll
                for (int j = 0; j < 8; ++j)
                    if (8 * tc + j > 8 * tr + i) s[i][j] = -1e30f;
        }

        // ---- online softmax (per-row stats across the 16-lane tc group) ----
        #pragma unroll
        for (int i = 0; i < 8; ++i) {
            float rm = s[i][0];
            #pragma unroll
            for (int j = 1; j < 8; ++j) rm = fmaxf(rm, s[i][j]);
            rm = fmaxf(rm, __shfl_xor_sync(0xffffffffu, rm, 1));
            rm = fmaxf(rm, __shfl_xor_sync(0xffffffffu, rm, 2));
            rm = fmaxf(rm, __shfl_xor_sync(0xffffffffu, rm, 4));
            rm = fmaxf(rm, __shfl_xor_sync(0xffffffffu, rm, 8));

            float mn   = fmaxf(m[i], rm);
            float corr = __expf(m[i] - mn);  // first tile: exp(-huge) = 0, no NaN
            m[i] = mn;

            float ps = 0.f;
            #pragma unroll
            for (int j = 0; j < 8; ++j) {
                float p = __expf(s[i][j] - mn);  // masked -> underflow to exactly 0
                s[i][j] = p;
                ps += p;
            }
            ps += __shfl_xor_sync(0xffffffffu, ps, 1);
            ps += __shfl_xor_sync(0xffffffffu, ps, 2);
            ps += __shfl_xor_sync(0xffffffffu, ps, 4);
            ps += __shfl_xor_sync(0xffffffffu, ps, 8);

            l[i] = l[i] * corr + ps;
            acc[i].x *= corr; acc[i].y *= corr; acc[i].z *= corr; acc[i].w *= corr;
        }

        // ---- stage P (swizzled); producers/consumers share the half-warp ----
        #pragma unroll
        for (int i = 0; i < 8; ++i) {
            int rb = (8 * tr + i) * PS;
            int c0 = 2 * tc, c1 = 2 * tc + 1;
            Ps[rb + ((c0 ^ (c0 >> 3)) ^ xq)] = make_float4(s[i][0], s[i][1], s[i][2], s[i][3]);
            Ps[rb + ((c1 ^ (c1 >> 3)) ^ xq)] = make_float4(s[i][4], s[i][5], s[i][6], s[i][7]);
        }
        __syncwarp();

        // ---- O += P V : 8 rows x 4 dims per thread ----
        #pragma unroll 4
        for (int g = 0; g < 32; ++g) {
            int pcol = (g ^ (g >> 3)) ^ xq;
            float4 p[8];
            #pragma unroll
            for (int i = 0; i < 8; ++i)
                p[i] = Ps[(8 * tr + i) * PS + pcol];
            int c = 4 * g;
            #pragma unroll
            for (int cc = 0; cc < 4; ++cc) {
                float4 v = Vs[(c + cc) * TS + tc];
                #pragma unroll
                for (int i = 0; i < 8; ++i) {
                    float pv = (cc == 0) ? p[i].x : (cc == 1) ? p[i].y
                             : (cc == 2) ? p[i].z : p[i].w;
                    acc[i].x += pv * v.x; acc[i].y += pv * v.y;
                    acc[i].z += pv * v.z; acc[i].w += pv * v.w;
                }
            }
        }
    }

    // ---- epilogue: normalize and store (coalesced f4) ----
    float4* Og = (float4*)O + ((size_t)(b * L_DIM + qt * BR)) * 256 + h * 16 + tc;
    #pragma unroll
    for (int i = 0; i < 8; ++i) {
        float inv = 1.0f / l[i];
        float4 o = acc[i];
        o.x *= inv; o.y *= inv; o.z *= inv; o.w *= inv;
        Og[(8 * tr + i) * 256] = o;
    }
}

extern "C" void kernel_launch(void* const* d_in, const int* in_sizes, int n_in,
                              void* d_out, int out_size)
{
    const float* Q = (const float*)d_in[0];
    const float* K = (const float*)d_in[1];
    const float* V = (const float*)d_in[2];
    float* O = (float*)d_out;

    cudaFuncSetAttribute(fa_causal_kernel,
                         cudaFuncAttributeMaxDynamicSharedMemorySize, SMEM_BYTES);

    dim3 grid(L_DIM / BR, H_DIM, 4);   // 16 x 16 x 4 = 1024 CTAs
    fa_causal_kernel<<<grid, NTH, SMEM_BYTES>>>(Q, K, V, O);
}